// round 1
// baseline (speedup 1.0000x reference)
#include <cuda_runtime.h>
#include <cstdint>
#include <math.h>

// Problem dims (fixed by the reference)
#define S_  256
#define B_  256
#define I_  256
#define H_  512
#define G4_ 2048
#define BH_ (B_ * H_)

// ---------------------------------------------------------------------------
// Scratch (device globals; no allocations allowed)
// ---------------------------------------------------------------------------
__device__ __align__(16) unsigned g_x_t32[S_ * B_ * I_];   // x pre-rounded to tf32
__device__ __align__(16) unsigned g_Wih0[G4_ * I_];
__device__ __align__(16) unsigned g_Whh0[G4_ * H_];
__device__ __align__(16) unsigned g_Wih1[G4_ * H_];
__device__ __align__(16) unsigned g_Whh1[G4_ * H_];

__device__ __align__(16) unsigned g_h0m_t32[2][BH_];   // masked h, tf32 mirror (ping-pong)
__device__ __align__(16) unsigned g_h1m_t32[2][BH_];
__device__ __align__(16) float    g_h0m_f32[2][BH_];   // masked h, fp32 (for final state out)
__device__ __align__(16) float    g_h1m_f32[2][BH_];
__device__ __align__(16) float    g_c0[2][BH_];
__device__ __align__(16) float    g_c1[2][BH_];
__device__ __align__(16) unsigned g_h0raw[BH_];        // pre-mask layer0 h (tf32) for layer1 input

// ---------------------------------------------------------------------------
// Helpers
// ---------------------------------------------------------------------------
__device__ __forceinline__ unsigned f2t(float f) {
    unsigned r;
    asm("cvt.rna.tf32.f32 %0, %1;" : "=r"(r) : "f"(f));
    return r;
}

__device__ __forceinline__ void cpa16(void* sp, const void* gp) {
    unsigned sa = (unsigned)__cvta_generic_to_shared(sp);
    asm volatile("cp.async.cg.shared.global [%0], [%1], 16;\n"
                 :: "r"(sa), "l"(gp) : "memory");
}
__device__ __forceinline__ void cpa_commit() {
    asm volatile("cp.async.commit_group;\n" ::: "memory");
}

__device__ __forceinline__ float sigmoidf_(float x) {
    return 1.0f / (1.0f + expf(-x));
}

// ---------------------------------------------------------------------------
// Prep: round fp32 arrays to tf32 (rna) once per launch
// ---------------------------------------------------------------------------
__global__ void conv_kernel(int which, const float* __restrict__ src, int n) {
    unsigned* dst = (which == 0) ? g_x_t32
                  : (which == 1) ? g_Wih0
                  : (which == 2) ? g_Whh0
                  : (which == 3) ? g_Wih1
                  :                g_Whh1;
    for (int i = blockIdx.x * blockDim.x + threadIdx.x; i < n;
         i += gridDim.x * blockDim.x)
        dst[i] = f2t(src[i]);
}

__global__ void init_kernel(const float* __restrict__ h0, const float* __restrict__ c0) {
    int i = blockIdx.x * blockDim.x + threadIdx.x;
    if (i < BH_) {
        float a = h0[i], b = h0[BH_ + i];
        g_h0m_f32[0][i] = a; g_h0m_t32[0][i] = f2t(a);
        g_h1m_f32[0][i] = b; g_h1m_t32[0][i] = f2t(b);
        g_c0[0][i] = c0[i];
        g_c1[0][i] = c0[BH_ + i];
    }
}

__global__ void final_kernel(float* __restrict__ out) {
    int i = blockIdx.x * blockDim.x + threadIdx.x;
    if (i < BH_) {
        size_t base = (size_t)S_ * B_ * H_;
        out[base + i]            = g_h0m_f32[0][i];   // h layer0
        out[base + BH_ + i]      = g_h1m_f32[0][i];   // h layer1
        out[base + 2 * BH_ + i]  = g_c0[0][i];        // c layer0
        out[base + 3 * BH_ + i]  = g_c1[0][i];        // c layer1
    }
}

// ---------------------------------------------------------------------------
// Fused step kernel: gates = A1@W1^T + A2@W2^T (+bias), then LSTM cell + mask.
// CTA tile: 32 batch rows x 32 hidden units (=> 4x32 = 128 gate columns).
// 4 warps, warp w owns gate w (32x32 output), TF32 mma.sync m16n8k8,
// K staged in 32-wide chunks with cp.async double buffering.
// Grid: (B/32, H/32) = (8, 16) = 128 CTAs.
// ---------------------------------------------------------------------------
#define KC_ 32

__global__ __launch_bounds__(128) void lstm_step(
    int t, int layer,
    const float* __restrict__ done_t,   // done_mask + t*B
    const float* __restrict__ ba,       // b_ih (2048)
    const float* __restrict__ bb,       // b_hh (2048)
    float* __restrict__ d_out)          // full output buffer
{
    // smem: A stage [2][32][36], B stage [2][128][36]; gates buffer overlays.
    __shared__ unsigned sm[2 * 32 * 36 + 2 * 128 * 36];   // 46080 B
    unsigned* sAbuf[2] = { sm, sm + 32 * 36 };
    unsigned* sBbuf[2] = { sm + 2 * 32 * 36, sm + 2 * 32 * 36 + 128 * 36 };

    const int rp = t & 1, wp = rp ^ 1;

    const unsigned *A1, *A2, *W1, *W2;
    int nch1, nch2, lda1, lda2, ldw1, ldw2;
    const float* c_in; float* c_out;
    unsigned* out_raw_t32; float* out_raw_f32;
    unsigned* out_m_t32;   float* out_m_f32;

    if (layer == 0) {
        A1 = g_h0m_t32[rp];                      lda1 = H_; W1 = g_Whh0; ldw1 = H_; nch1 = H_ / KC_;
        A2 = g_x_t32 + (size_t)t * B_ * I_;      lda2 = I_; W2 = g_Wih0; ldw2 = I_; nch2 = I_ / KC_;
        c_in = g_c0[rp]; c_out = g_c0[wp];
        out_raw_t32 = g_h0raw; out_raw_f32 = nullptr;
        out_m_t32 = g_h0m_t32[wp]; out_m_f32 = g_h0m_f32[wp];
    } else {
        A1 = g_h0raw;                            lda1 = H_; W1 = g_Wih1; ldw1 = H_; nch1 = H_ / KC_;
        A2 = g_h1m_t32[rp];                      lda2 = H_; W2 = g_Whh1; ldw2 = H_; nch2 = H_ / KC_;
        c_in = g_c1[rp]; c_out = g_c1[wp];
        out_raw_t32 = nullptr; out_raw_f32 = d_out + (size_t)t * B_ * H_;
        out_m_t32 = g_h1m_t32[wp]; out_m_f32 = g_h1m_f32[wp];
    }
    const int nch = nch1 + nch2;

    const int m0  = blockIdx.x * 32;
    const int j0  = blockIdx.y * 32;
    const int tid = threadIdx.x;
    const int w   = tid >> 5;
    const int lane = tid & 31;
    const int grp = lane >> 2;
    const int tig = lane & 3;

    auto stage = [&](int kc, int buf) {
        const unsigned* As; const unsigned* Ws; int kk, la, lw;
        if (kc < nch1) { As = A1; Ws = W1; kk = kc * KC_;          la = lda1; lw = ldw1; }
        else           { As = A2; Ws = W2; kk = (kc - nch1) * KC_; la = lda2; lw = ldw2; }
        // A tile: 32 x 32 floats -> 256 float4 -> 2 per thread
        #pragma unroll
        for (int i = 0; i < 2; i++) {
            int idx = tid + i * 128; int m = idx >> 3; int c = (idx & 7) * 4;
            cpa16(&sAbuf[buf][m * 36 + c], As + (size_t)(m0 + m) * la + kk + c);
        }
        // B tile: 128 gate-rows x 32 k -> 1024 float4 -> 8 per thread
        #pragma unroll
        for (int i = 0; i < 8; i++) {
            int idx = tid + i * 128; int nn = idx >> 3; int c = (idx & 7) * 4;
            int wr = (nn >> 5) * H_ + j0 + (nn & 31);   // gate*(H) + hidden col
            cpa16(&sBbuf[buf][nn * 36 + c], Ws + (size_t)wr * lw + kk + c);
        }
    };

    float acc[2][4][4];
    #pragma unroll
    for (int r = 0; r < 2; r++)
        #pragma unroll
        for (int nf = 0; nf < 4; nf++)
            #pragma unroll
            for (int c = 0; c < 4; c++) acc[r][nf][c] = 0.f;

    stage(0, 0); cpa_commit();
    stage(1, 1); cpa_commit();

    for (int kc = 0; kc < nch; kc++) {
        if (kc + 1 < nch) { asm volatile("cp.async.wait_group 1;\n" ::: "memory"); }
        else              { asm volatile("cp.async.wait_group 0;\n" ::: "memory"); }
        __syncthreads();

        const int buf = kc & 1;
        const unsigned* pA = sAbuf[buf];
        const unsigned* pB = sBbuf[buf];

        #pragma unroll
        for (int ks = 0; ks < 4; ks++) {
            const int kb = ks * 8;
            unsigned a[2][4];
            #pragma unroll
            for (int r = 0; r < 2; r++) {
                int mr = r * 16 + grp;
                a[r][0] = pA[mr * 36 + kb + tig];
                a[r][1] = pA[(mr + 8) * 36 + kb + tig];
                a[r][2] = pA[mr * 36 + kb + tig + 4];
                a[r][3] = pA[(mr + 8) * 36 + kb + tig + 4];
            }
            #pragma unroll
            for (int nf = 0; nf < 4; nf++) {
                int nr = w * 32 + nf * 8 + grp;
                unsigned b0 = pB[nr * 36 + kb + tig];
                unsigned b1 = pB[nr * 36 + kb + tig + 4];
                #pragma unroll
                for (int r = 0; r < 2; r++) {
                    asm volatile(
                        "mma.sync.aligned.m16n8k8.row.col.f32.tf32.tf32.f32 "
                        "{%0,%1,%2,%3}, {%4,%5,%6,%7}, {%8,%9}, {%0,%1,%2,%3};"
                        : "+f"(acc[r][nf][0]), "+f"(acc[r][nf][1]),
                          "+f"(acc[r][nf][2]), "+f"(acc[r][nf][3])
                        : "r"(a[r][0]), "r"(a[r][1]), "r"(a[r][2]), "r"(a[r][3]),
                          "r"(b0), "r"(b1));
                }
            }
        }
        __syncthreads();
        if (kc + 2 < nch) { stage(kc + 2, buf); cpa_commit(); }
    }

    // Epilogue: gates -> smem (reuse stage buffers; all cp.async drained) -> cell
    float* sG = (float*)sm;  // [128 rows = gate*32+m][33]
    #pragma unroll
    for (int r = 0; r < 2; r++)
        #pragma unroll
        for (int nf = 0; nf < 4; nf++)
            #pragma unroll
            for (int c = 0; c < 4; c++) {
                int row = r * 16 + grp + ((c & 2) ? 8 : 0);
                int col = nf * 8 + tig * 2 + (c & 1);
                sG[(w * 32 + row) * 33 + col] = acc[r][nf][c];
            }
    __syncthreads();

    #pragma unroll
    for (int i = 0; i < 8; i++) {
        int idx = i * 128 + tid;
        int m = idx >> 5, j = idx & 31;
        int gm = m0 + m, gj = j0 + j;

        float iv = sG[(0 * 32 + m) * 33 + j] + ba[0 * H_ + gj] + bb[0 * H_ + gj];
        float fv = sG[(1 * 32 + m) * 33 + j] + ba[1 * H_ + gj] + bb[1 * H_ + gj];
        float gv = sG[(2 * 32 + m) * 33 + j] + ba[2 * H_ + gj] + bb[2 * H_ + gj];
        float ov = sG[(3 * 32 + m) * 33 + j] + ba[3 * H_ + gj] + bb[3 * H_ + gj];

        float ii = sigmoidf_(iv);
        float ff = sigmoidf_(fv);
        float gg = tanhf(gv);
        float oo = sigmoidf_(ov);

        size_t off = (size_t)gm * H_ + gj;
        float cp = c_in[off];
        float cn = ff * cp + ii * gg;
        float hn = oo * tanhf(cn);

        if (out_raw_f32) out_raw_f32[off] = hn;       // outputs[t] (pre-mask, top layer)
        if (out_raw_t32) out_raw_t32[off] = f2t(hn);  // layer1 input (pre-mask)

        float msk = 1.0f - done_t[gm];
        float hm = hn * msk, cm = cn * msk;
        c_out[off]     = cm;
        out_m_f32[off] = hm;
        out_m_t32[off] = f2t(hm);
    }
}

// ---------------------------------------------------------------------------
// Launch
// ---------------------------------------------------------------------------
extern "C" void kernel_launch(void* const* d_in, const int* in_sizes, int n_in,
                              void* d_out, int out_size) {
    const float* x    = (const float*)d_in[0];
    const float* h0   = (const float*)d_in[1];
    const float* c0   = (const float*)d_in[2];
    const float* done = (const float*)d_in[3];
    const float* Wih0 = (const float*)d_in[4];
    const float* Whh0 = (const float*)d_in[5];
    const float* bih0 = (const float*)d_in[6];
    const float* bhh0 = (const float*)d_in[7];
    const float* Wih1 = (const float*)d_in[8];
    const float* Whh1 = (const float*)d_in[9];
    const float* bih1 = (const float*)d_in[10];
    const float* bhh1 = (const float*)d_in[11];
    float* out = (float*)d_out;

    conv_kernel<<<512, 256>>>(0, x,    S_ * B_ * I_);
    conv_kernel<<<256, 256>>>(1, Wih0, G4_ * I_);
    conv_kernel<<<256, 256>>>(2, Whh0, G4_ * H_);
    conv_kernel<<<256, 256>>>(3, Wih1, G4_ * H_);
    conv_kernel<<<256, 256>>>(4, Whh1, G4_ * H_);
    init_kernel<<<(BH_ + 255) / 256, 256>>>(h0, c0);

    dim3 grid(B_ / 32, H_ / 32);   // (8, 16)
    for (int t = 0; t < S_; t++) {
        lstm_step<<<grid, 128>>>(t, 0, done + (size_t)t * B_, bih0, bhh0, out);
        lstm_step<<<grid, 128>>>(t, 1, done + (size_t)t * B_, bih1, bhh1, out);
    }
    final_kernel<<<(BH_ + 255) / 256, 256>>>(out);
}

// round 2
// speedup vs baseline: 1.1552x; 1.1552x over previous
#include <cuda_runtime.h>
#include <cstdint>
#include <math.h>

// Problem dims (fixed by the reference)
#define S_  256
#define B_  256
#define I_  256
#define H_  512
#define G4_ 2048
#define BH_ (B_ * H_)

// ---------------------------------------------------------------------------
// Scratch (device globals; no allocations allowed)
// ---------------------------------------------------------------------------
__device__ __align__(16) unsigned g_x_t32[S_ * B_ * I_];   // x pre-rounded to tf32
__device__ __align__(16) unsigned g_Wih0[G4_ * I_];
__device__ __align__(16) unsigned g_Whh0[G4_ * H_];
__device__ __align__(16) unsigned g_Wih1[G4_ * H_];
__device__ __align__(16) unsigned g_Whh1[G4_ * H_];
__device__ float g_bias[2][G4_];                           // b_ih + b_hh per layer

__device__ __align__(16) unsigned g_h0m_t32[2][BH_];   // masked h, tf32 mirror (ping-pong)
__device__ __align__(16) unsigned g_h1m_t32[2][BH_];
__device__ __align__(16) float    g_h0m_f32[2][BH_];   // masked h, fp32 (final state out)
__device__ __align__(16) float    g_h1m_f32[2][BH_];
__device__ __align__(16) float    g_c0[2][BH_];
__device__ __align__(16) float    g_c1[2][BH_];
__device__ __align__(16) unsigned g_h0raw[2][BH_];     // pre-mask layer0 h (tf32), dbl-buffered

// ---------------------------------------------------------------------------
// Helpers
// ---------------------------------------------------------------------------
__device__ __forceinline__ unsigned f2t(float f) {
    unsigned r;
    asm("cvt.rna.tf32.f32 %0, %1;" : "=r"(r) : "f"(f));
    return r;
}

__device__ __forceinline__ void cpa16(void* sp, const void* gp) {
    unsigned sa = (unsigned)__cvta_generic_to_shared(sp);
    asm volatile("cp.async.cg.shared.global [%0], [%1], 16;\n"
                 :: "r"(sa), "l"(gp) : "memory");
}
__device__ __forceinline__ void cpa_commit() {
    asm volatile("cp.async.commit_group;\n" ::: "memory");
}

__device__ __forceinline__ float sigm_(float x) {
    return 1.0f / (1.0f + __expf(-x));
}
__device__ __forceinline__ float tanh_(float x) {
    float a = fabsf(x);
    float t = __expf(-2.0f * a);
    float r = (1.0f - t) / (1.0f + t);
    return copysignf(r, x);
}

// ---------------------------------------------------------------------------
// Prep kernels
// ---------------------------------------------------------------------------
__global__ void conv_kernel(int which, const float* __restrict__ src, int n) {
    unsigned* dst = (which == 0) ? g_x_t32
                  : (which == 1) ? g_Wih0
                  : (which == 2) ? g_Whh0
                  : (which == 3) ? g_Wih1
                  :                g_Whh1;
    for (int i = blockIdx.x * blockDim.x + threadIdx.x; i < n;
         i += gridDim.x * blockDim.x)
        dst[i] = f2t(src[i]);
}

__global__ void bias_kernel(const float* __restrict__ bi0, const float* __restrict__ bh0,
                            const float* __restrict__ bi1, const float* __restrict__ bh1) {
    int i = blockIdx.x * blockDim.x + threadIdx.x;
    if (i < G4_) {
        g_bias[0][i] = bi0[i] + bh0[i];
        g_bias[1][i] = bi1[i] + bh1[i];
    }
}

__global__ void init_kernel(const float* __restrict__ h0, const float* __restrict__ c0) {
    int i = blockIdx.x * blockDim.x + threadIdx.x;
    if (i < BH_) {
        float a = h0[i], b = h0[BH_ + i];
        g_h0m_f32[0][i] = a; g_h0m_t32[0][i] = f2t(a);
        g_h1m_f32[0][i] = b; g_h1m_t32[0][i] = f2t(b);
        g_c0[0][i] = c0[i];
        g_c1[0][i] = c0[BH_ + i];
    }
}

__global__ void final_kernel(float* __restrict__ out) {
    int i = blockIdx.x * blockDim.x + threadIdx.x;
    if (i < BH_) {
        size_t base = (size_t)S_ * B_ * H_;
        out[base + i]            = g_h0m_f32[0][i];   // h layer0
        out[base + BH_ + i]      = g_h1m_f32[0][i];   // h layer1
        out[base + 2 * BH_ + i]  = g_c0[0][i];        // c layer0
        out[base + 3 * BH_ + i]  = g_c1[0][i];        // c layer1
    }
}

// ---------------------------------------------------------------------------
// Fused PHASE kernel: at phase p, runs layer0 at t=p (CTAs 0..63) and
// layer1 at t=p-1 (CTAs 64..127) concurrently — they are independent.
// CTA tile: 64 batch x 32 hidden (=> 128 gate columns). 8 warps, warp tile
// 32 x 32 (wm = m half, wg = gate). TF32 mma.sync m16n8k8, K chunks of 32,
// 4-stage cp.async pipeline.
// ---------------------------------------------------------------------------
#define KC_    32
#define NST_   4
#define SM_A_  (64 * 36)                 // 2304 words
#define SM_B_  (128 * 36)                // 4608 words
#define SM_STG (SM_A_ + SM_B_)           // 6912 words = 27648 B
#define SMEM_BYTES (NST_ * SM_STG * 4)   // 110592 B

__global__ __launch_bounds__(256, 1) void lstm_phase(
    int p,
    const float* __restrict__ done,     // (S, B)
    float* __restrict__ d_out)
{
    extern __shared__ unsigned sm[];

    const int sub = blockIdx.x >> 6;      // 0: layer0@t=p, 1: layer1@t=p-1
    if (sub == 0 && p == S_) return;
    if (sub == 1 && p == 0)  return;
    const int t  = (sub == 0) ? p : (p - 1);
    const int rp = t & 1, wp = rp ^ 1;

    const unsigned *A1, *A2, *W1, *W2;
    int nch1, nch2, lda1, lda2, ldw1, ldw2;
    const float* c_in; float* c_out;
    unsigned* out_raw_t32; float* out_raw_f32;
    unsigned* out_m_t32;   float* out_m_f32;

    if (sub == 0) {
        A1 = g_h0m_t32[rp];                  lda1 = H_; W1 = g_Whh0; ldw1 = H_; nch1 = H_ / KC_;
        A2 = g_x_t32 + (size_t)t * B_ * I_;  lda2 = I_; W2 = g_Wih0; ldw2 = I_; nch2 = I_ / KC_;
        c_in = g_c0[rp]; c_out = g_c0[wp];
        out_raw_t32 = g_h0raw[rp]; out_raw_f32 = nullptr;
        out_m_t32 = g_h0m_t32[wp]; out_m_f32 = g_h0m_f32[wp];
    } else {
        A1 = g_h0raw[rp];                    lda1 = H_; W1 = g_Wih1; ldw1 = H_; nch1 = H_ / KC_;
        A2 = g_h1m_t32[rp];                  lda2 = H_; W2 = g_Whh1; ldw2 = H_; nch2 = H_ / KC_;
        c_in = g_c1[rp]; c_out = g_c1[wp];
        out_raw_t32 = nullptr; out_raw_f32 = d_out + (size_t)t * B_ * H_;
        out_m_t32 = g_h1m_t32[wp]; out_m_f32 = g_h1m_f32[wp];
    }
    const int nch = nch1 + nch2;

    const int cta = blockIdx.x & 63;
    const int m0  = (cta & 3) * 64;       // batch tile
    const int j0  = (cta >> 2) * 32;      // hidden tile
    const int tid = threadIdx.x;
    const int wid = tid >> 5;
    const int wm  = wid & 1;              // m half (32 rows)
    const int wg  = wid >> 1;             // gate (0..3)
    const int lane = tid & 31;
    const int grp = lane >> 2;
    const int tig = lane & 3;

    unsigned* bufA[NST_]; unsigned* bufB[NST_];
    #pragma unroll
    for (int s = 0; s < NST_; s++) { bufA[s] = sm + s * SM_STG; bufB[s] = bufA[s] + SM_A_; }

    auto stage = [&](int kc, int buf) {
        const unsigned* As; const unsigned* Ws; int kk, la, lw;
        if (kc < nch1) { As = A1; Ws = W1; kk = kc * KC_;          la = lda1; lw = ldw1; }
        else           { As = A2; Ws = W2; kk = (kc - nch1) * KC_; la = lda2; lw = ldw2; }
        unsigned* sA = bufA[buf]; unsigned* sB = bufB[buf];
        // A: 64 rows x 32 k = 512 float4 / 256 thr = 2 each
        #pragma unroll
        for (int i = 0; i < 2; i++) {
            int idx = tid + i * 256; int m = idx >> 3; int c = (idx & 7) * 4;
            cpa16(&sA[m * 36 + c], As + (size_t)(m0 + m) * la + kk + c);
        }
        // B: 128 gate rows x 32 k = 1024 float4 / 256 thr = 4 each
        #pragma unroll
        for (int i = 0; i < 4; i++) {
            int idx = tid + i * 256; int nn = idx >> 3; int c = (idx & 7) * 4;
            int wr = (nn >> 5) * H_ + j0 + (nn & 31);
            cpa16(&sB[nn * 36 + c], Ws + (size_t)wr * lw + kk + c);
        }
    };

    float acc[2][4][4];
    #pragma unroll
    for (int r = 0; r < 2; r++)
        #pragma unroll
        for (int nf = 0; nf < 4; nf++)
            #pragma unroll
            for (int c = 0; c < 4; c++) acc[r][nf][c] = 0.f;

    stage(0, 0); cpa_commit();
    stage(1, 1); cpa_commit();
    stage(2, 2); cpa_commit();

    for (int kc = 0; kc < nch; kc++) {
        asm volatile("cp.async.wait_group 2;\n" ::: "memory");
        __syncthreads();
        if (kc + 3 < nch) stage(kc + 3, (kc + 3) & 3);
        cpa_commit();

        const unsigned* pA = bufA[kc & 3];
        const unsigned* pB = bufB[kc & 3];

        #pragma unroll
        for (int ks = 0; ks < 4; ks++) {
            const int kb = ks * 8;
            unsigned a[2][4];
            #pragma unroll
            for (int r = 0; r < 2; r++) {
                int mr = wm * 32 + r * 16 + grp;
                a[r][0] = pA[mr * 36 + kb + tig];
                a[r][1] = pA[(mr + 8) * 36 + kb + tig];
                a[r][2] = pA[mr * 36 + kb + tig + 4];
                a[r][3] = pA[(mr + 8) * 36 + kb + tig + 4];
            }
            #pragma unroll
            for (int nf = 0; nf < 4; nf++) {
                int nr = wg * 32 + nf * 8 + grp;
                unsigned b0 = pB[nr * 36 + kb + tig];
                unsigned b1 = pB[nr * 36 + kb + tig + 4];
                #pragma unroll
                for (int r = 0; r < 2; r++) {
                    asm volatile(
                        "mma.sync.aligned.m16n8k8.row.col.f32.tf32.tf32.f32 "
                        "{%0,%1,%2,%3}, {%4,%5,%6,%7}, {%8,%9}, {%0,%1,%2,%3};"
                        : "+f"(acc[r][nf][0]), "+f"(acc[r][nf][1]),
                          "+f"(acc[r][nf][2]), "+f"(acc[r][nf][3])
                        : "r"(a[r][0]), "r"(a[r][1]), "r"(a[r][2]), "r"(a[r][3]),
                          "r"(b0), "r"(b1));
                }
            }
        }
    }

    asm volatile("cp.async.wait_group 0;\n" ::: "memory");
    __syncthreads();

    // Epilogue: gates -> smem (reuse stage buffers) -> LSTM cell
    float* sG = (float*)sm;   // [gate*64 + m][33], 256*33 = 8448 words
    #pragma unroll
    for (int r = 0; r < 2; r++)
        #pragma unroll
        for (int nf = 0; nf < 4; nf++)
            #pragma unroll
            for (int c = 0; c < 4; c++) {
                int row = wm * 32 + r * 16 + grp + ((c & 2) ? 8 : 0);
                int col = nf * 8 + tig * 2 + (c & 1);
                sG[(wg * 64 + row) * 33 + col] = acc[r][nf][c];
            }
    __syncthreads();

    const float* bs = g_bias[sub];
    const float* done_t = done + (size_t)t * B_;

    #pragma unroll
    for (int i = 0; i < 8; i++) {
        int idx = i * 256 + tid;
        int m = idx >> 5, j = idx & 31;
        int gm = m0 + m, gj = j0 + j;

        float iv = sG[(0 * 64 + m) * 33 + j] + bs[0 * H_ + gj];
        float fv = sG[(1 * 64 + m) * 33 + j] + bs[1 * H_ + gj];
        float gv = sG[(2 * 64 + m) * 33 + j] + bs[2 * H_ + gj];
        float ov = sG[(3 * 64 + m) * 33 + j] + bs[3 * H_ + gj];

        float ii = sigm_(iv);
        float ff = sigm_(fv);
        float gg = tanh_(gv);
        float oo = sigm_(ov);

        size_t off = (size_t)gm * H_ + gj;
        float cp = c_in[off];
        float cn = ff * cp + ii * gg;
        float hn = oo * tanh_(cn);

        if (out_raw_f32) out_raw_f32[off] = hn;       // outputs[t] (pre-mask, top layer)
        if (out_raw_t32) out_raw_t32[off] = f2t(hn);  // layer1 input (pre-mask)

        float msk = 1.0f - done_t[gm];
        float hm = hn * msk, cm = cn * msk;
        c_out[off]     = cm;
        out_m_f32[off] = hm;
        out_m_t32[off] = f2t(hm);
    }
}

// ---------------------------------------------------------------------------
// Launch
// ---------------------------------------------------------------------------
extern "C" void kernel_launch(void* const* d_in, const int* in_sizes, int n_in,
                              void* d_out, int out_size) {
    const float* x    = (const float*)d_in[0];
    const float* h0   = (const float*)d_in[1];
    const float* c0   = (const float*)d_in[2];
    const float* done = (const float*)d_in[3];
    const float* Wih0 = (const float*)d_in[4];
    const float* Whh0 = (const float*)d_in[5];
    const float* bih0 = (const float*)d_in[6];
    const float* bhh0 = (const float*)d_in[7];
    const float* Wih1 = (const float*)d_in[8];
    const float* Whh1 = (const float*)d_in[9];
    const float* bih1 = (const float*)d_in[10];
    const float* bhh1 = (const float*)d_in[11];
    float* out = (float*)d_out;

    cudaFuncSetAttribute(lstm_phase, cudaFuncAttributeMaxDynamicSharedMemorySize,
                         SMEM_BYTES);

    conv_kernel<<<512, 256>>>(0, x,    S_ * B_ * I_);
    conv_kernel<<<256, 256>>>(1, Wih0, G4_ * I_);
    conv_kernel<<<256, 256>>>(2, Whh0, G4_ * H_);
    conv_kernel<<<256, 256>>>(3, Wih1, G4_ * H_);
    conv_kernel<<<256, 256>>>(4, Whh1, G4_ * H_);
    bias_kernel<<<(G4_ + 255) / 256, 256>>>(bih0, bhh0, bih1, bhh1);
    init_kernel<<<(BH_ + 255) / 256, 256>>>(h0, c0);

    for (int p = 0; p <= S_; p++) {
        lstm_phase<<<128, 256, SMEM_BYTES>>>(p, done, out);
    }
    final_kernel<<<(BH_ + 255) / 256, 256>>>(out);
}

// round 4
// speedup vs baseline: 2.4636x; 2.1326x over previous
#include <cuda_runtime.h>
#include <cuda_fp16.h>
#include <cstdint>
#include <math.h>

// Problem dims (fixed by the reference)
#define S_  256
#define B_  256
#define I_  256
#define H_  512
#define G4_ 2048
#define BH_ (B_ * H_)

// ---------------------------------------------------------------------------
// Scratch (device globals; no allocations allowed)
// ---------------------------------------------------------------------------
__device__ __align__(16) __half g_x_h[S_ * B_ * I_];   // x pre-rounded to fp16
__device__ __align__(16) __half g_Wih0[G4_ * I_];
__device__ __align__(16) __half g_Whh0[G4_ * H_];
__device__ __align__(16) __half g_Wih1[G4_ * H_];
__device__ __align__(16) __half g_Whh1[G4_ * H_];
__device__ float g_bias[2][G4_];                       // b_ih + b_hh per layer

__device__ __align__(16) __half g_h0m_h[2][BH_];   // masked h, fp16 mirror (ping-pong)
__device__ __align__(16) __half g_h1m_h[2][BH_];
__device__ __align__(16) float  g_h0m_f32[2][BH_]; // masked h, fp32 (final state out)
__device__ __align__(16) float  g_h1m_f32[2][BH_];
__device__ __align__(16) float  g_c0[2][BH_];
__device__ __align__(16) float  g_c1[2][BH_];
__device__ __align__(16) __half g_h0raw[2][BH_];   // pre-mask layer0 h (fp16), dbl-buffered

// ---------------------------------------------------------------------------
// Helpers
// ---------------------------------------------------------------------------
__device__ __forceinline__ void cpa16(void* sp, const void* gp) {
    unsigned sa = (unsigned)__cvta_generic_to_shared(sp);
    asm volatile("cp.async.cg.shared.global [%0], [%1], 16;\n"
                 :: "r"(sa), "l"(gp) : "memory");
}
__device__ __forceinline__ void cpa_commit() {
    asm volatile("cp.async.commit_group;\n" ::: "memory");
}
__device__ __forceinline__ float sigm_(float x) {
    return 1.0f / (1.0f + __expf(-x));
}
__device__ __forceinline__ float tanh_(float x) {
    float a = fabsf(x);
    float t = __expf(-2.0f * a);
    float r = (1.0f - t) / (1.0f + t);
    return copysignf(r, x);
}
__device__ __forceinline__ void ldsm4(unsigned& r0, unsigned& r1, unsigned& r2,
                                      unsigned& r3, unsigned addr) {
    asm volatile("ldmatrix.sync.aligned.m8n8.x4.shared.b16 {%0,%1,%2,%3}, [%4];"
                 : "=r"(r0), "=r"(r1), "=r"(r2), "=r"(r3) : "r"(addr));
}

// ---------------------------------------------------------------------------
// Prep kernels
// ---------------------------------------------------------------------------
__global__ void conv_kernel(int which, const float* __restrict__ src, int n) {
    __half* dst = (which == 0) ? g_x_h
                : (which == 1) ? g_Wih0
                : (which == 2) ? g_Whh0
                : (which == 3) ? g_Wih1
                :                g_Whh1;
    for (int i = blockIdx.x * blockDim.x + threadIdx.x; i < n;
         i += gridDim.x * blockDim.x)
        dst[i] = __float2half_rn(src[i]);
}

__global__ void bias_kernel(const float* __restrict__ bi0, const float* __restrict__ bh0,
                            const float* __restrict__ bi1, const float* __restrict__ bh1) {
    int i = blockIdx.x * blockDim.x + threadIdx.x;
    if (i < G4_) {
        g_bias[0][i] = bi0[i] + bh0[i];
        g_bias[1][i] = bi1[i] + bh1[i];
    }
}

__global__ void init_kernel(const float* __restrict__ h0, const float* __restrict__ c0) {
    int i = blockIdx.x * blockDim.x + threadIdx.x;
    if (i < BH_) {
        float a = h0[i], b = h0[BH_ + i];
        g_h0m_f32[0][i] = a; g_h0m_h[0][i] = __float2half_rn(a);
        g_h1m_f32[0][i] = b; g_h1m_h[0][i] = __float2half_rn(b);
        g_c0[0][i] = c0[i];
        g_c1[0][i] = c0[BH_ + i];
    }
}

__global__ void final_kernel(float* __restrict__ out) {
    int i = blockIdx.x * blockDim.x + threadIdx.x;
    if (i < BH_) {
        size_t base = (size_t)S_ * B_ * H_;
        out[base + i]            = g_h0m_f32[0][i];   // h layer0
        out[base + BH_ + i]      = g_h1m_f32[0][i];   // h layer1
        out[base + 2 * BH_ + i]  = g_c0[0][i];        // c layer0
        out[base + 3 * BH_ + i]  = g_c1[0][i];        // c layer1
    }
}

// ---------------------------------------------------------------------------
// Fused PHASE kernel: phase p runs layer0@t=p (CTAs 0..63) and layer1@t=p-1
// (CTAs 64..127) concurrently. CTA tile: 64 batch x 32 hidden (128 gate cols).
// 8 warps, warp tile 32x32 (wm = m half, wg = gate). FP16 mma m16n8k16 with
// ldmatrix.x4 operand loads; K chunks of 64, 4-stage cp.async pipeline.
// Smem rows padded to 72 halfs (144B) -> conflict-free ldmatrix.
// ---------------------------------------------------------------------------
#define KC_    64
#define LDR_   72                          // padded row length in halfs
#define SM_A_H (64 * LDR_)                 // 4608 halfs
#define SM_B_H (128 * LDR_)                // 9216 halfs
#define SM_STG (SM_A_H + SM_B_H)           // 13824 halfs = 27648 B
#define NST_   4
#define SMEM_BYTES (NST_ * SM_STG * 2)     // 110592 B

__global__ __launch_bounds__(256, 1) void lstm_phase(
    int p,
    const float* __restrict__ done,     // (S, B)
    float* __restrict__ d_out)
{
    extern __shared__ __half sm[];

    const int sub = blockIdx.x >> 6;      // 0: layer0@t=p, 1: layer1@t=p-1
    if (sub == 0 && p == S_) return;
    if (sub == 1 && p == 0)  return;
    const int t  = (sub == 0) ? p : (p - 1);
    const int rp = t & 1, wp = rp ^ 1;

    const __half *A1, *A2, *W1, *W2;
    int nch1, nch2, lda1, lda2, ldw1, ldw2;
    const float* c_in; float* c_out;
    __half* out_raw_h; float* out_raw_f32;
    __half* out_m_h;   float* out_m_f32;

    if (sub == 0) {
        A1 = g_h0m_h[rp];                   lda1 = H_; W1 = g_Whh0; ldw1 = H_; nch1 = H_ / KC_;
        A2 = g_x_h + (size_t)t * B_ * I_;   lda2 = I_; W2 = g_Wih0; ldw2 = I_; nch2 = I_ / KC_;
        c_in = g_c0[rp]; c_out = g_c0[wp];
        out_raw_h = g_h0raw[rp]; out_raw_f32 = nullptr;
        out_m_h = g_h0m_h[wp]; out_m_f32 = g_h0m_f32[wp];
    } else {
        A1 = g_h0raw[rp];                   lda1 = H_; W1 = g_Wih1; ldw1 = H_; nch1 = H_ / KC_;
        A2 = g_h1m_h[rp];                   lda2 = H_; W2 = g_Whh1; ldw2 = H_; nch2 = H_ / KC_;
        c_in = g_c1[rp]; c_out = g_c1[wp];
        out_raw_h = nullptr; out_raw_f32 = d_out + (size_t)t * B_ * H_;
        out_m_h = g_h1m_h[wp]; out_m_f32 = g_h1m_f32[wp];
    }
    const int nch = nch1 + nch2;

    const int cta = blockIdx.x & 63;
    const int m0  = (cta & 3) * 64;       // batch tile
    const int j0  = (cta >> 2) * 32;      // hidden tile
    const int tid = threadIdx.x;
    const int wid = tid >> 5;
    const int wm  = wid & 1;              // m half (32 rows)
    const int wg  = wid >> 1;             // gate (0..3)
    const int lane = tid & 31;
    const int grp = lane >> 2;
    const int tig = lane & 3;

    // ldmatrix per-lane address patterns
    const int mat   = lane >> 3;
    const int mrow  = (mat & 1) * 8 + (lane & 7);   // A: row within 16, col-block (mat>>1)*8
    const int mcol  = (mat >> 1) * 8;
    const int brow  = (mat >> 1) * 8 + (lane & 7);  // B: row within 16, col-block (mat&1)*8
    const int bcol  = (mat & 1) * 8;

    unsigned bufAu[NST_], bufBu[NST_];
    #pragma unroll
    for (int s = 0; s < NST_; s++) {
        bufAu[s] = (unsigned)__cvta_generic_to_shared(sm + s * SM_STG);
        bufBu[s] = bufAu[s] + SM_A_H * 2;
    }

    auto stage = [&](int kc, int buf) {
        const __half* As; const __half* Ws; int kk, la, lw;
        if (kc < nch1) { As = A1; Ws = W1; kk = kc * KC_;          la = lda1; lw = ldw1; }
        else           { As = A2; Ws = W2; kk = (kc - nch1) * KC_; la = lda2; lw = ldw2; }
        __half* sA = sm + buf * SM_STG;
        __half* sB = sA + SM_A_H;
        // A: 64 rows x 64 halfs = 512 x 16B chunks / 256 thr = 2 each
        #pragma unroll
        for (int i = 0; i < 2; i++) {
            int idx = tid + i * 256; int m = idx >> 3; int c = (idx & 7) * 8;
            cpa16(&sA[m * LDR_ + c], As + (size_t)(m0 + m) * la + kk + c);
        }
        // B: 128 gate rows x 64 halfs = 1024 chunks / 256 thr = 4 each
        #pragma unroll
        for (int i = 0; i < 4; i++) {
            int idx = tid + i * 256; int nn = idx >> 3; int c = (idx & 7) * 8;
            int wr = (nn >> 5) * H_ + j0 + (nn & 31);
            cpa16(&sB[nn * LDR_ + c], Ws + (size_t)wr * lw + kk + c);
        }
    };

    float acc[2][4][4];
    #pragma unroll
    for (int r = 0; r < 2; r++)
        #pragma unroll
        for (int nf = 0; nf < 4; nf++)
            #pragma unroll
            for (int c = 0; c < 4; c++) acc[r][nf][c] = 0.f;

    stage(0, 0); cpa_commit();
    stage(1, 1); cpa_commit();
    stage(2, 2); cpa_commit();

    for (int kc = 0; kc < nch; kc++) {
        asm volatile("cp.async.wait_group 2;\n" ::: "memory");
        __syncthreads();
        if (kc + 3 < nch) stage(kc + 3, (kc + 3) & 3);
        cpa_commit();

        const unsigned pAu = bufAu[kc & 3];
        const unsigned pBu = bufBu[kc & 3];

        #pragma unroll
        for (int ks = 0; ks < 4; ks++) {
            unsigned a[2][4];
            #pragma unroll
            for (int r = 0; r < 2; r++) {
                int row = wm * 32 + r * 16 + mrow;
                unsigned ad = pAu + (unsigned)(row * LDR_ + mcol + ks * 16) * 2;
                ldsm4(a[r][0], a[r][1], a[r][2], a[r][3], ad);
            }
            unsigned bb[2][4];
            #pragma unroll
            for (int pq = 0; pq < 2; pq++) {
                int row = wg * 32 + pq * 16 + brow;
                unsigned ad = pBu + (unsigned)(row * LDR_ + bcol + ks * 16) * 2;
                ldsm4(bb[pq][0], bb[pq][1], bb[pq][2], bb[pq][3], ad);
            }
            #pragma unroll
            for (int nf = 0; nf < 4; nf++) {
                unsigned b0 = bb[nf >> 1][(nf & 1) * 2];
                unsigned b1 = bb[nf >> 1][(nf & 1) * 2 + 1];
                #pragma unroll
                for (int r = 0; r < 2; r++) {
                    asm volatile(
                        "mma.sync.aligned.m16n8k16.row.col.f32.f16.f16.f32 "
                        "{%0,%1,%2,%3}, {%4,%5,%6,%7}, {%8,%9}, {%0,%1,%2,%3};"
                        : "+f"(acc[r][nf][0]), "+f"(acc[r][nf][1]),
                          "+f"(acc[r][nf][2]), "+f"(acc[r][nf][3])
                        : "r"(a[r][0]), "r"(a[r][1]), "r"(a[r][2]), "r"(a[r][3]),
                          "r"(b0), "r"(b1));
                }
            }
        }
    }

    asm volatile("cp.async.wait_group 0;\n" ::: "memory");
    __syncthreads();

    // Epilogue: gates -> smem (reuse stage buffers) -> LSTM cell
    float* sG = (float*)sm;   // [gate*64 + m][33], 256*33 floats = 33792 B
    #pragma unroll
    for (int r = 0; r < 2; r++)
        #pragma unroll
        for (int nf = 0; nf < 4; nf++)
            #pragma unroll
            for (int c = 0; c < 4; c++) {
                int row = wm * 32 + r * 16 + grp + ((c & 2) ? 8 : 0);
                int col = nf * 8 + tig * 2 + (c & 1);
                sG[(wg * 64 + row) * 33 + col] = acc[r][nf][c];
            }
    __syncthreads();

    const float* bs = g_bias[sub];
    const float* done_t = done + (size_t)t * B_;

    #pragma unroll
    for (int i = 0; i < 8; i++) {
        int idx = i * 256 + tid;
        int m = idx >> 5, j = idx & 31;
        int gm = m0 + m, gj = j0 + j;

        // Hoist latency-bound global loads above the smem gate reads
        size_t off = (size_t)gm * H_ + gj;
        float cp  = c_in[off];
        float msk = 1.0f - done_t[gm];

        float iv = sG[(0 * 64 + m) * 33 + j] + bs[0 * H_ + gj];
        float fv = sG[(1 * 64 + m) * 33 + j] + bs[1 * H_ + gj];
        float gv = sG[(2 * 64 + m) * 33 + j] + bs[2 * H_ + gj];
        float ov = sG[(3 * 64 + m) * 33 + j] + bs[3 * H_ + gj];

        float ii = sigm_(iv);
        float ff = sigm_(fv);
        float gg = tanh_(gv);
        float oo = sigm_(ov);

        float cn = ff * cp + ii * gg;
        float hn = oo * tanh_(cn);

        if (out_raw_f32) out_raw_f32[off] = hn;                  // outputs[t] (pre-mask)
        if (out_raw_h)   out_raw_h[off]   = __float2half_rn(hn); // layer1 input (pre-mask)

        float hm = hn * msk, cm = cn * msk;
        c_out[off]     = cm;
        out_m_f32[off] = hm;
        out_m_h[off]   = __float2half_rn(hm);
    }
}

// ---------------------------------------------------------------------------
// Launch
// ---------------------------------------------------------------------------
extern "C" void kernel_launch(void* const* d_in, const int* in_sizes, int n_in,
                              void* d_out, int out_size) {
    const float* x    = (const float*)d_in[0];
    const float* h0   = (const float*)d_in[1];
    const float* c0   = (const float*)d_in[2];
    const float* done = (const float*)d_in[3];
    const float* Wih0 = (const float*)d_in[4];
    const float* Whh0 = (const float*)d_in[5];
    const float* bih0 = (const float*)d_in[6];
    const float* bhh0 = (const float*)d_in[7];
    const float* Wih1 = (const float*)d_in[8];
    const float* Whh1 = (const float*)d_in[9];
    const float* bih1 = (const float*)d_in[10];
    const float* bhh1 = (const float*)d_in[11];
    float* out = (float*)d_out;

    cudaFuncSetAttribute(lstm_phase, cudaFuncAttributeMaxDynamicSharedMemorySize,
                         SMEM_BYTES);

    conv_kernel<<<512, 256>>>(0, x,    S_ * B_ * I_);
    conv_kernel<<<256, 256>>>(1, Wih0, G4_ * I_);
    conv_kernel<<<256, 256>>>(2, Whh0, G4_ * H_);
    conv_kernel<<<256, 256>>>(3, Wih1, G4_ * H_);
    conv_kernel<<<256, 256>>>(4, Whh1, G4_ * H_);
    bias_kernel<<<(G4_ + 255) / 256, 256>>>(bih0, bhh0, bih1, bhh1);
    init_kernel<<<(BH_ + 255) / 256, 256>>>(h0, c0);

    for (int p = 0; p <= S_; p++) {
        lstm_phase<<<128, 256, SMEM_BYTES>>>(p, done, out);
    }
    final_kernel<<<(BH_ + 255) / 256, 256>>>(out);
}

// round 6
// speedup vs baseline: 2.8326x; 1.1498x over previous
#include <cuda_runtime.h>
#include <cuda_fp16.h>
#include <cstdint>
#include <math.h>

// Problem dims (fixed by the reference)
#define S_  256
#define B_  256
#define I_  256
#define H_  512
#define G4_ 2048
#define BH_ (B_ * H_)

// ---------------------------------------------------------------------------
// Scratch (device globals; no allocations allowed)
// ---------------------------------------------------------------------------
__device__ __align__(16) __half g_x_h[S_ * B_ * I_];   // x pre-rounded to fp16
__device__ __align__(16) __half g_Wih0[G4_ * I_];
__device__ __align__(16) __half g_Whh0[G4_ * H_];
__device__ __align__(16) __half g_Wih1[G4_ * H_];
__device__ __align__(16) __half g_Whh1[G4_ * H_];
__device__ float g_bias[2][G4_];                       // b_ih + b_hh per layer

__device__ __align__(16) __half g_h0m_h[2][BH_];   // masked h, fp16 mirror (ping-pong)
__device__ __align__(16) __half g_h1m_h[2][BH_];
__device__ __align__(16) float  g_h0m_f32[2][BH_]; // masked h, fp32 (final state out)
__device__ __align__(16) float  g_h1m_f32[2][BH_];
__device__ __align__(16) float  g_c0[2][BH_];
__device__ __align__(16) float  g_c1[2][BH_];
__device__ __align__(16) __half g_h0raw[2][BH_];   // pre-mask layer0 h (fp16), dbl-buffered

// ---------------------------------------------------------------------------
// Helpers
// ---------------------------------------------------------------------------
__device__ __forceinline__ void cpa16(void* sp, const void* gp) {
    unsigned sa = (unsigned)__cvta_generic_to_shared(sp);
    asm volatile("cp.async.cg.shared.global [%0], [%1], 16;\n"
                 :: "r"(sa), "l"(gp) : "memory");
}
__device__ __forceinline__ void cpa_commit() {
    asm volatile("cp.async.commit_group;\n" ::: "memory");
}
__device__ __forceinline__ float sigm_(float x) {
    return 1.0f / (1.0f + __expf(-x));
}
__device__ __forceinline__ float tanh_(float x) {
    float a = fabsf(x);
    float t = __expf(-2.0f * a);
    float r = (1.0f - t) / (1.0f + t);
    return copysignf(r, x);
}
__device__ __forceinline__ void ldsm4(unsigned& r0, unsigned& r1, unsigned& r2,
                                      unsigned& r3, unsigned addr) {
    asm volatile("ldmatrix.sync.aligned.m8n8.x4.shared.b16 {%0,%1,%2,%3}, [%4];"
                 : "=r"(r0), "=r"(r1), "=r"(r2), "=r"(r3) : "r"(addr));
}

// ---------------------------------------------------------------------------
// Prep: ONE fused kernel (keeps launch count low so ncu -s 5 profiles
// lstm_phase). grid-stride over the largest array; each range converted.
// ---------------------------------------------------------------------------
__global__ void prep_kernel(const float* __restrict__ x,
                            const float* __restrict__ Wih0, const float* __restrict__ Whh0,
                            const float* __restrict__ Wih1, const float* __restrict__ Whh1,
                            const float* __restrict__ bi0, const float* __restrict__ bh0,
                            const float* __restrict__ bi1, const float* __restrict__ bh1) {
    const int stride = gridDim.x * blockDim.x;
    const int tid0 = blockIdx.x * blockDim.x + threadIdx.x;
    for (int i = tid0; i < S_ * B_ * I_; i += stride) g_x_h[i] = __float2half_rn(x[i]);
    for (int i = tid0; i < G4_ * I_; i += stride) g_Wih0[i] = __float2half_rn(Wih0[i]);
    for (int i = tid0; i < G4_ * H_; i += stride) {
        g_Whh0[i] = __float2half_rn(Whh0[i]);
        g_Wih1[i] = __float2half_rn(Wih1[i]);
        g_Whh1[i] = __float2half_rn(Whh1[i]);
    }
    for (int i = tid0; i < G4_; i += stride) {
        g_bias[0][i] = bi0[i] + bh0[i];
        g_bias[1][i] = bi1[i] + bh1[i];
    }
}

__global__ void init_kernel(const float* __restrict__ h0, const float* __restrict__ c0) {
    int i = blockIdx.x * blockDim.x + threadIdx.x;
    if (i < BH_) {
        float a = h0[i], b = h0[BH_ + i];
        g_h0m_f32[0][i] = a; g_h0m_h[0][i] = __float2half_rn(a);
        g_h1m_f32[0][i] = b; g_h1m_h[0][i] = __float2half_rn(b);
        g_c0[0][i] = c0[i];
        g_c1[0][i] = c0[BH_ + i];
    }
}

__global__ void final_kernel(float* __restrict__ out) {
    int i = blockIdx.x * blockDim.x + threadIdx.x;
    if (i < BH_) {
        size_t base = (size_t)S_ * B_ * H_;
        out[base + i]            = g_h0m_f32[0][i];   // h layer0
        out[base + BH_ + i]      = g_h1m_f32[0][i];   // h layer1
        out[base + 2 * BH_ + i]  = g_c0[0][i];        // c layer0
        out[base + 3 * BH_ + i]  = g_c1[0][i];        // c layer1
    }
}

// ---------------------------------------------------------------------------
// Fused PHASE kernel: phase p runs layer0@t=p (CTAs 0..63) and layer1@t=p-1
// (CTAs 64..127) concurrently. CTA tile: 64 batch x 32 hidden (128 gate cols).
// 8 warps, warp tile 32x32 (wm = m half, wg = gate). FP16 mma m16n8k16 with
// ldmatrix.x4 operand loads; K chunks of 128, 4-stage cp.async pipeline
// (~204KB dyn smem) -> single barrier per chunk, 3-chunk prefetch distance.
// Rows padded to 136 halfs (272B = 4-bank offset/row) -> conflict-free ldsm.
// ---------------------------------------------------------------------------
#define KC_    128
#define LDR_   136                         // padded row length in halfs
#define SM_A_H (64 * LDR_)                 // 8704 halfs
#define SM_B_H (128 * LDR_)                // 17408 halfs
#define SM_STG (SM_A_H + SM_B_H)           // 26112 halfs = 52224 B
#define NST_   4
#define SMEM_BYTES (NST_ * SM_STG * 2)     // 208896 B

__global__ __launch_bounds__(256, 1) void lstm_phase(
    int p,
    const float* __restrict__ done,     // (S, B)
    float* __restrict__ d_out)
{
    extern __shared__ __half sm[];

    const int sub = blockIdx.x >> 6;      // 0: layer0@t=p, 1: layer1@t=p-1
    if (sub == 0 && p == S_) return;
    if (sub == 1 && p == 0)  return;
    const int t  = (sub == 0) ? p : (p - 1);
    const int rp = t & 1, wp = rp ^ 1;

    const __half *A1, *A2, *W1, *W2;
    int nch1, nch2, lda1, lda2, ldw1, ldw2;
    const float* c_in; float* c_out;
    __half* out_raw_h; float* out_raw_f32;
    __half* out_m_h;   float* out_m_f32;

    if (sub == 0) {
        A1 = g_h0m_h[rp];                   lda1 = H_; W1 = g_Whh0; ldw1 = H_; nch1 = H_ / KC_;
        A2 = g_x_h + (size_t)t * B_ * I_;   lda2 = I_; W2 = g_Wih0; ldw2 = I_; nch2 = I_ / KC_;
        c_in = g_c0[rp]; c_out = g_c0[wp];
        out_raw_h = g_h0raw[rp]; out_raw_f32 = nullptr;
        out_m_h = g_h0m_h[wp]; out_m_f32 = g_h0m_f32[wp];
    } else {
        A1 = g_h0raw[rp];                   lda1 = H_; W1 = g_Wih1; ldw1 = H_; nch1 = H_ / KC_;
        A2 = g_h1m_h[rp];                   lda2 = H_; W2 = g_Whh1; ldw2 = H_; nch2 = H_ / KC_;
        c_in = g_c1[rp]; c_out = g_c1[wp];
        out_raw_h = nullptr; out_raw_f32 = d_out + (size_t)t * B_ * H_;
        out_m_h = g_h1m_h[wp]; out_m_f32 = g_h1m_f32[wp];
    }
    const int nch = nch1 + nch2;          // 6 (layer0) or 8 (layer1)

    const int cta = blockIdx.x & 63;
    const int m0  = (cta & 3) * 64;       // batch tile
    const int j0  = (cta >> 2) * 32;      // hidden tile
    const int tid = threadIdx.x;
    const int wid = tid >> 5;
    const int wm  = wid & 1;              // m half (32 rows)
    const int wg  = wid >> 1;             // gate (0..3)
    const int lane = tid & 31;
    const int grp = lane >> 2;
    const int tig = lane & 3;

    // ldmatrix per-lane address patterns
    const int mat   = lane >> 3;
    const int mrow  = (mat & 1) * 8 + (lane & 7);   // A: row within 16, col-block (mat>>1)*8
    const int mcol  = (mat >> 1) * 8;
    const int brow  = (mat >> 1) * 8 + (lane & 7);  // B: row within 16, col-block (mat&1)*8
    const int bcol  = (mat & 1) * 8;

    unsigned bufAu[NST_], bufBu[NST_];
    #pragma unroll
    for (int s = 0; s < NST_; s++) {
        bufAu[s] = (unsigned)__cvta_generic_to_shared(sm + s * SM_STG);
        bufBu[s] = bufAu[s] + SM_A_H * 2;
    }

    auto stage = [&](int kc, int buf) {
        const __half* As; const __half* Ws; int kk, la, lw;
        if (kc < nch1) { As = A1; Ws = W1; kk = kc * KC_;          la = lda1; lw = ldw1; }
        else           { As = A2; Ws = W2; kk = (kc - nch1) * KC_; la = lda2; lw = ldw2; }
        __half* sA = sm + buf * SM_STG;
        __half* sB = sA + SM_A_H;
        // A: 64 rows x 128 halfs = 1024 x 16B chunks / 256 thr = 4 each
        #pragma unroll
        for (int i = 0; i < 4; i++) {
            int idx = tid + i * 256; int m = idx >> 4; int c = (idx & 15) * 8;
            cpa16(&sA[m * LDR_ + c], As + (size_t)(m0 + m) * la + kk + c);
        }
        // B: 128 gate rows x 128 halfs = 2048 chunks / 256 thr = 8 each
        #pragma unroll
        for (int i = 0; i < 8; i++) {
            int idx = tid + i * 256; int nn = idx >> 4; int c = (idx & 15) * 8;
            int wr = (nn >> 5) * H_ + j0 + (nn & 31);
            cpa16(&sB[nn * LDR_ + c], Ws + (size_t)wr * lw + kk + c);
        }
    };

    float acc[2][4][4];
    #pragma unroll
    for (int r = 0; r < 2; r++)
        #pragma unroll
        for (int nf = 0; nf < 4; nf++)
            #pragma unroll
            for (int c = 0; c < 4; c++) acc[r][nf][c] = 0.f;

    stage(0, 0); cpa_commit();
    stage(1, 1); cpa_commit();
    stage(2, 2); cpa_commit();

    for (int kc = 0; kc < nch; kc++) {
        asm volatile("cp.async.wait_group 2;\n" ::: "memory");
        __syncthreads();
        if (kc + 3 < nch) stage(kc + 3, (kc + 3) & 3);
        cpa_commit();

        const unsigned pAu = bufAu[kc & 3];
        const unsigned pBu = bufBu[kc & 3];

        #pragma unroll
        for (int ks = 0; ks < 8; ks++) {
            unsigned a[2][4];
            #pragma unroll
            for (int r = 0; r < 2; r++) {
                int row = wm * 32 + r * 16 + mrow;
                unsigned ad = pAu + (unsigned)(row * LDR_ + mcol + ks * 16) * 2;
                ldsm4(a[r][0], a[r][1], a[r][2], a[r][3], ad);
            }
            unsigned bb[2][4];
            #pragma unroll
            for (int pq = 0; pq < 2; pq++) {
                int row = wg * 32 + pq * 16 + brow;
                unsigned ad = pBu + (unsigned)(row * LDR_ + bcol + ks * 16) * 2;
                ldsm4(bb[pq][0], bb[pq][1], bb[pq][2], bb[pq][3], ad);
            }
            #pragma unroll
            for (int nf = 0; nf < 4; nf++) {
                unsigned b0 = bb[nf >> 1][(nf & 1) * 2];
                unsigned b1 = bb[nf >> 1][(nf & 1) * 2 + 1];
                #pragma unroll
                for (int r = 0; r < 2; r++) {
                    asm volatile(
                        "mma.sync.aligned.m16n8k16.row.col.f32.f16.f16.f32 "
                        "{%0,%1,%2,%3}, {%4,%5,%6,%7}, {%8,%9}, {%0,%1,%2,%3};"
                        : "+f"(acc[r][nf][0]), "+f"(acc[r][nf][1]),
                          "+f"(acc[r][nf][2]), "+f"(acc[r][nf][3])
                        : "r"(a[r][0]), "r"(a[r][1]), "r"(a[r][2]), "r"(a[r][3]),
                          "r"(b0), "r"(b1));
                }
            }
        }
    }

    asm volatile("cp.async.wait_group 0;\n" ::: "memory");
    __syncthreads();

    // Epilogue: gates -> smem (reuse stage buffers) -> LSTM cell
    float* sG = (float*)sm;   // [gate*64 + m][33], 256*33 floats = 33792 B
    #pragma unroll
    for (int r = 0; r < 2; r++)
        #pragma unroll
        for (int nf = 0; nf < 4; nf++)
            #pragma unroll
            for (int c = 0; c < 4; c++) {
                int row = wm * 32 + r * 16 + grp + ((c & 2) ? 8 : 0);
                int col = nf * 8 + tig * 2 + (c & 1);
                sG[(wg * 64 + row) * 33 + col] = acc[r][nf][c];
            }
    __syncthreads();

    const float* bs = g_bias[sub];
    const float* done_t = done + (size_t)t * B_;

    #pragma unroll
    for (int i = 0; i < 8; i++) {
        int idx = i * 256 + tid;
        int m = idx >> 5, j = idx & 31;
        int gm = m0 + m, gj = j0 + j;

        // Hoist latency-bound global loads above the smem gate reads
        size_t off = (size_t)gm * H_ + gj;
        float cp  = c_in[off];
        float msk = 1.0f - done_t[gm];

        float iv = sG[(0 * 64 + m) * 33 + j] + bs[0 * H_ + gj];
        float fv = sG[(1 * 64 + m) * 33 + j] + bs[1 * H_ + gj];
        float gv = sG[(2 * 64 + m) * 33 + j] + bs[2 * H_ + gj];
        float ov = sG[(3 * 64 + m) * 33 + j] + bs[3 * H_ + gj];

        float ii = sigm_(iv);
        float ff = sigm_(fv);
        float gg = tanh_(gv);
        float oo = sigm_(ov);

        float cn = ff * cp + ii * gg;
        float hn = oo * tanh_(cn);

        if (out_raw_f32) out_raw_f32[off] = hn;                  // outputs[t] (pre-mask)
        if (out_raw_h)   out_raw_h[off]   = __float2half_rn(hn); // layer1 input (pre-mask)

        float hm = hn * msk, cm = cn * msk;
        c_out[off]     = cm;
        out_m_f32[off] = hm;
        out_m_h[off]   = __float2half_rn(hm);
    }
}

// ---------------------------------------------------------------------------
// Launch
// ---------------------------------------------------------------------------
extern "C" void kernel_launch(void* const* d_in, const int* in_sizes, int n_in,
                              void* d_out, int out_size) {
    const float* x    = (const float*)d_in[0];
    const float* h0   = (const float*)d_in[1];
    const float* c0   = (const float*)d_in[2];
    const float* done = (const float*)d_in[3];
    const float* Wih0 = (const float*)d_in[4];
    const float* Whh0 = (const float*)d_in[5];
    const float* bih0 = (const float*)d_in[6];
    const float* bhh0 = (const float*)d_in[7];
    const float* Wih1 = (const float*)d_in[8];
    const float* Whh1 = (const float*)d_in[9];
    const float* bih1 = (const float*)d_in[10];
    const float* bhh1 = (const float*)d_in[11];
    float* out = (float*)d_out;

    cudaFuncSetAttribute(lstm_phase, cudaFuncAttributeMaxDynamicSharedMemorySize,
                         SMEM_BYTES);

    prep_kernel<<<592, 256>>>(x, Wih0, Whh0, Wih1, Whh1, bih0, bhh0, bih1, bhh1);
    init_kernel<<<(BH_ + 255) / 256, 256>>>(h0, c0);

    for (int p = 0; p <= S_; p++) {
        lstm_phase<<<128, 256, SMEM_BYTES>>>(p, done, out);
    }
    final_kernel<<<(BH_ + 255) / 256, 256>>>(out);
}